// round 11
// baseline (speedup 1.0000x reference)
#include <cuda_runtime.h>
#include <stdint.h>
#include <math.h>

#define NB 64
#define NC 512
#define HW 1024
#define NE 16
#define TABLE 65536          // 65536 floats per expert (2048*32)

// ---------------- scratch (allocation-free: __device__ globals) ----------------
__device__ float g_x[NB * NC];     // pooled activations
__device__ int   g_i0[NB];         // top-1 expert per batch
__device__ int   g_i1[NB];         // top-2 expert per batch
__device__ float g_p0[NB];         // top-1 prob
__device__ float g_p1[NB];         // top-2 prob
__device__ float g_z[NB];          // lse^2 per batch

// ---------------- threefry2x32 (JAX-compatible) ----------------
__device__ __forceinline__ uint32_t rotl32(uint32_t x, int d) {
    return (x << d) | (x >> (32 - d));
}

__device__ __forceinline__ void threefry2x32(uint32_t k0, uint32_t k1,
                                             uint32_t x0, uint32_t x1,
                                             uint32_t* o0, uint32_t* o1) {
    const uint32_t ks0 = k0, ks1 = k1, ks2 = k0 ^ k1 ^ 0x1BD11BDAu;
    uint32_t a = x0 + ks0, b = x1 + ks1;
    const int r0[4] = {13, 15, 26, 6};
    const int r1[4] = {17, 29, 16, 24};
#define TF_ROUND4(R) \
    { a += b; b = rotl32(b, (R)[0]); b ^= a; \
      a += b; b = rotl32(b, (R)[1]); b ^= a; \
      a += b; b = rotl32(b, (R)[2]); b ^= a; \
      a += b; b = rotl32(b, (R)[3]); b ^= a; }
    TF_ROUND4(r0); a += ks1; b += ks2 + 1u;
    TF_ROUND4(r1); a += ks2; b += ks0 + 2u;
    TF_ROUND4(r0); a += ks0; b += ks1 + 3u;
    TF_ROUND4(r1); a += ks1; b += ks2 + 4u;
    TF_ROUND4(r0); a += ks2; b += ks0 + 5u;
#undef TF_ROUND4
    *o0 = a; *o1 = b;
}

// eps[j] for flat j in [0, 1024): jax.random.normal(key(42), (64,16))
__device__ __forceinline__ float jax_normal_eps(int j) {
    uint32_t o0, o1, bits;
    if (j < 512) {
        threefry2x32(0u, 42u, (uint32_t)j, (uint32_t)(j + 512), &o0, &o1);
        bits = o0;
    } else {
        threefry2x32(0u, 42u, (uint32_t)(j - 512), (uint32_t)j, &o0, &o1);
        bits = o1;
    }
    float f = __uint_as_float((bits >> 9) | 0x3f800000u) - 1.0f;   // [0,1)
    const float lo = __uint_as_float(0xBF7FFFFFu);                 // nextafter(-1,0)
    float u = fmaxf(lo, f * 2.0f + lo);                            // hi-lo == 2.0f
    return 1.4142135623730951f * erfinvf(u);
}

__device__ __forceinline__ float softplus_f(float x) {
    return fmaxf(x, 0.0f) + log1pf(expf(-fabsf(x)));
}

// ---------------- Kernel A: mean pool, 2 rows per warp (MLP=16) ----------------
__global__ void __launch_bounds__(256) k_pool(const float* __restrict__ in) {
    const int tid = threadIdx.x;
    const int warp = tid >> 5, lane = tid & 31;
    const int row0 = blockIdx.x * 16 + warp * 2;

    const float4* p0 = (const float4*)(in + (size_t)row0 * HW);
    const float4* p1 = (const float4*)(in + (size_t)(row0 + 1) * HW);

    float4 v0[8], v1[8];
#pragma unroll
    for (int i = 0; i < 8; i++) v0[i] = __ldcs(&p0[lane + i * 32]);
#pragma unroll
    for (int i = 0; i < 8; i++) v1[i] = __ldcs(&p1[lane + i * 32]);

    float s0 = 0.0f, s1 = 0.0f;
#pragma unroll
    for (int i = 0; i < 8; i++) {
        s0 += (v0[i].x + v0[i].y) + (v0[i].z + v0[i].w);
        s1 += (v1[i].x + v1[i].y) + (v1[i].z + v1[i].w);
    }
#pragma unroll
    for (int o = 16; o > 0; o >>= 1) {
        s0 += __shfl_down_sync(0xffffffffu, s0, o);
        s1 += __shfl_down_sync(0xffffffffu, s1, o);
    }
    if (lane == 0) {
        g_x[row0]     = s0 * (1.0f / 1024.0f);
        g_x[row0 + 1] = s1 * (1.0f / 1024.0f);
    }
}

// ---------------- Kernel B: dual GEMV + router; PDL prologue prefetches W ----------------
__global__ void __launch_bounds__(256) k_gemv_router(
    const float* __restrict__ Wr, const float* __restrict__ br,
    const float* __restrict__ Wn, const float* __restrict__ bn)
{
    const int b = blockIdx.x, tid = threadIdx.x;
    const int warp = tid >> 5, lane = tid & 31;

    // ---- PDL prologue: prefetch W rows (independent of pool) ----
    const float4* Wr4 = (const float4*)Wr;
    const float4* Wn4 = (const float4*)Wn;
    const int c0 = warp * 64 + lane;      // this thread's two rows
    const int c1 = c0 + 32;
    float4 wr0[4], wr1[4], wn0[4], wn1[4];
#pragma unroll
    for (int i = 0; i < 4; i++) {
        wr0[i] = __ldg(&Wr4[c0 * 4 + i]);
        wn0[i] = __ldg(&Wn4[c0 * 4 + i]);
        wr1[i] = __ldg(&Wr4[c1 * 4 + i]);
        wn1[i] = __ldg(&Wn4[c1 * 4 + i]);
    }

    // wait for pool's g_x writes
    cudaGridDependencySynchronize();

    __shared__ float xs[NC];
    __shared__ float part_r[8][NE];
    __shared__ float part_n[8][NE];
    if (tid < 128) ((float4*)xs)[tid] = ((const float4*)(g_x + b * NC))[tid];
    __syncthreads();

    float ar[NE], an[NE];
#pragma unroll
    for (int e = 0; e < NE; e++) { ar[e] = 0.0f; an[e] = 0.0f; }

    float x0 = xs[c0], x1 = xs[c1];
#pragma unroll
    for (int i = 0; i < 4; i++) {
        ar[i*4+0] = fmaf(x0, wr0[i].x, fmaf(x1, wr1[i].x, ar[i*4+0]));
        ar[i*4+1] = fmaf(x0, wr0[i].y, fmaf(x1, wr1[i].y, ar[i*4+1]));
        ar[i*4+2] = fmaf(x0, wr0[i].z, fmaf(x1, wr1[i].z, ar[i*4+2]));
        ar[i*4+3] = fmaf(x0, wr0[i].w, fmaf(x1, wr1[i].w, ar[i*4+3]));
        an[i*4+0] = fmaf(x0, wn0[i].x, fmaf(x1, wn1[i].x, an[i*4+0]));
        an[i*4+1] = fmaf(x0, wn0[i].y, fmaf(x1, wn1[i].y, an[i*4+1]));
        an[i*4+2] = fmaf(x0, wn0[i].z, fmaf(x1, wn1[i].z, an[i*4+2]));
        an[i*4+3] = fmaf(x0, wn0[i].w, fmaf(x1, wn1[i].w, an[i*4+3]));
    }
#pragma unroll
    for (int o = 16; o > 0; o >>= 1) {
#pragma unroll
        for (int e = 0; e < NE; e++) {
            ar[e] += __shfl_xor_sync(0xffffffffu, ar[e], o);
            an[e] += __shfl_xor_sync(0xffffffffu, an[e], o);
        }
    }
    if (lane == 0) {
#pragma unroll
        for (int e = 0; e < NE; e++) { part_r[warp][e] = ar[e]; part_n[warp][e] = an[e]; }
    }
    __syncthreads();

    // ---- router: warp 0, lanes 0..15 = experts ----
    if (warp == 0) {
        bool act = lane < NE;
        float lg = 0.0f, nz = 0.0f;
        if (act) {
#pragma unroll
            for (int w = 0; w < 8; w++) { lg += part_r[w][lane]; nz += part_n[w][lane]; }
            lg += __ldg(&br[lane]);
            nz += __ldg(&bn[lane]);
        }
        if (!act) lg = -INFINITY;

        float m = lg;
#pragma unroll
        for (int o = 16; o > 0; o >>= 1) m = fmaxf(m, __shfl_xor_sync(0xffffffffu, m, o));
        float el = act ? expf(lg - m) : 0.0f;
        float s = el;
#pragma unroll
        for (int o = 16; o > 0; o >>= 1) s += __shfl_xor_sync(0xffffffffu, s, o);
        float soft = el / s;

        float pre = -INFINITY;
        if (act) {
            float eps = jax_normal_eps(b * NE + lane);
            pre = eps * softplus_f(nz);
        }
        float m2 = pre;
#pragma unroll
        for (int o = 16; o > 0; o >>= 1) m2 = fmaxf(m2, __shfl_xor_sync(0xffffffffu, m2, o));
        float ep = act ? expf(pre - m2) : 0.0f;
        float s2 = ep;
#pragma unroll
        for (int o = 16; o > 0; o >>= 1) s2 += __shfl_xor_sync(0xffffffffu, s2, o);

        float ny = act ? (soft + ep / s2) : -INFINITY;

        float v0 = ny; int i0 = lane;
#pragma unroll
        for (int o = 16; o > 0; o >>= 1) {
            float vo = __shfl_xor_sync(0xffffffffu, v0, o);
            int io = __shfl_xor_sync(0xffffffffu, i0, o);
            if (vo > v0 || (vo == v0 && io < i0)) { v0 = vo; i0 = io; }
        }
        float v1 = (lane == i0) ? -INFINITY : ny; int i1 = lane;
#pragma unroll
        for (int o = 16; o > 0; o >>= 1) {
            float vo = __shfl_xor_sync(0xffffffffu, v1, o);
            int io = __shfl_xor_sync(0xffffffffu, i1, o);
            if (vo > v1 || (vo == v1 && io < i1)) { v1 = vo; i1 = io; }
        }

        float ee = act ? expf(ny - v0) : 0.0f;
        float ss = ee;
#pragma unroll
        for (int o = 16; o > 0; o >>= 1) ss += __shfl_xor_sync(0xffffffffu, ss, o);

        if (lane == 0) {
            float lse = v0 + logf(ss);
            float e1 = expf(v1 - v0);
            float p0 = 1.0f / (1.0f + e1);
            g_i0[b] = i0; g_i1[b] = i1;
            g_p0[b] = p0; g_p1[b] = e1 * p0;
            g_z[b]  = lse * lse;
        }
    }
}

// ---------------- Kernel C: combine; PDL prologue prefetches A into registers ----------------
__global__ void __launch_bounds__(128) k_combine(const float* __restrict__ A,
                                                 float* __restrict__ out) {
    const int t = threadIdx.x;
    const int idx = blockIdx.x * blockDim.x + t;   // float4 index, 16384 total

    // ---- PDL prologue: prefetch A (independent of gemv/router) ----
    const float4* A4 = (const float4*)A;
    float4 v[NE];
#pragma unroll
    for (int e = 0; e < NE; e++)
        v[e] = __ldg(&A4[(size_t)e * (TABLE / 4) + idx]);

    // wait for router outputs
    cudaGridDependencySynchronize();

    __shared__ int   si0[NB], si1[NB];
    __shared__ float sp0[NB], sp1[NB];
    __shared__ float ws[NE];
    if (t < NB) {
        si0[t] = g_i0[t]; si1[t] = g_i1[t];
        sp0[t] = g_p0[t]; sp1[t] = g_p1[t];
    }
    __syncthreads();
    if (t < NE) {
        float w = 0.0f;
#pragma unroll 8
        for (int b = 0; b < NB; b++) {
            if (si0[b] == t) w += sp0[b];
            if (si1[b] == t) w += sp1[b];
        }
        ws[t] = w * (1.0f / (float)NB);
    }
    if (blockIdx.x == 0 && t == 64) {
        float z = 0.0f;
#pragma unroll
        for (int b = 0; b < NB; b++) z += g_z[b];
        out[TABLE] = z * (1.0f / (float)NB);
    }
    __syncthreads();

    float4 acc = make_float4(0.f, 0.f, 0.f, 0.f);
#pragma unroll
    for (int e = 0; e < NE; e++) {
        float w = ws[e];
        acc.x = fmaf(w, v[e].x, acc.x);
        acc.y = fmaf(w, v[e].y, acc.y);
        acc.z = fmaf(w, v[e].z, acc.z);
        acc.w = fmaf(w, v[e].w, acc.w);
    }
    ((float4*)out)[idx] = acc;
}

// ---------------- launch (PDL chain: pool -> gemv -> combine) ----------------
extern "C" void kernel_launch(void* const* d_in, const int* in_sizes, int n_in,
                              void* d_out, int out_size) {
    const float* inputs  = (const float*)d_in[0];  // [64,512,32,32]
    const float* W_route = (const float*)d_in[1];  // [512,16]
    const float* b_route = (const float*)d_in[2];  // [16]
    const float* W_noise = (const float*)d_in[3];  // [512,16]
    const float* b_noise = (const float*)d_in[4];  // [16]
    const float* A_logs  = (const float*)d_in[5];  // [16,2048,32]
    float* out = (float*)d_out;

    k_pool<<<2048, 256>>>(inputs);

    cudaLaunchAttribute attr[1];
    attr[0].id = cudaLaunchAttributeProgrammaticStreamSerialization;
    attr[0].val.programmaticStreamSerializationAllowed = 1;

    {
        cudaLaunchConfig_t cfg = {};
        cfg.gridDim = dim3(NB, 1, 1);
        cfg.blockDim = dim3(256, 1, 1);
        cfg.attrs = attr;
        cfg.numAttrs = 1;
        cudaLaunchKernelEx(&cfg, k_gemv_router, W_route, b_route, W_noise, b_noise);
    }
    {
        cudaLaunchConfig_t cfg = {};
        cfg.gridDim = dim3((TABLE / 4) / 128, 1, 1);
        cfg.blockDim = dim3(128, 1, 1);
        cfg.attrs = attr;
        cfg.numAttrs = 1;
        cudaLaunchKernelEx(&cfg, k_combine, A_logs, out);
    }
}